// round 1
// baseline (speedup 1.0000x reference)
#include <cuda_runtime.h>
#include <cuda_bf16.h>
#include <math.h>

// Problem constants
#define BATCH   2
#define SEQ     2048
#define DMODEL  1024
#define NHEADS  16
#define DK      64
#define MTOT    (BATCH * SEQ)          // 4096

// Scratch (device globals; no allocation allowed)
__device__ float g_Q[BATCH * NHEADS * SEQ * DK];     // [B,H,S,DK]
__device__ float g_K[BATCH * NHEADS * SEQ * DK];
__device__ float g_V[BATCH * NHEADS * SEQ * DK];
__device__ float g_ATT[MTOT * DMODEL];               // [B,S,H*DK]

// ---------------------------------------------------------------------------
// GEMM: Y = X @ W^T.  X [M,1024] row-major, W [1024,1024] row-major (out,in).
// MODE 0: scatter output into [B,H,S,DK] layout (for Q/K/V projections)
// MODE 1: plain [M,1024] output
// Tile: BM=BN=128, BK=16, 256 threads, 8x8 per thread.
// ---------------------------------------------------------------------------
template <int MODE>
__global__ __launch_bounds__(256)
void gemm_xwt_kernel(const float* __restrict__ X,
                     const float* __restrict__ W,
                     float* __restrict__ Y)
{
    __shared__ float As[16][128];   // A transposed: As[k][m]
    __shared__ float Bs[16][128];   // B transposed: Bs[k][n]

    const int t  = threadIdx.x;
    const int tx = t & 15;          // 0..15 (cols)
    const int ty = t >> 4;          // 0..15 (rows)
    const int bm = blockIdx.y * 128;
    const int bn = blockIdx.x * 128;

    float acc[8][8];
#pragma unroll
    for (int i = 0; i < 8; ++i)
#pragma unroll
        for (int j = 0; j < 8; ++j) acc[i][j] = 0.f;

    for (int k0 = 0; k0 < DMODEL; k0 += 16) {
        // Each thread loads 2 float4 from X and 2 from W (512 float4 each tile)
#pragma unroll
        for (int i = 0; i < 2; ++i) {
            int idx = t + i * 256;          // 0..511
            int r   = idx >> 2;             // 0..127
            int c4  = idx & 3;              // which float4 in the 16-wide k slab
            float4 a = *(const float4*)&X[(size_t)(bm + r) * DMODEL + k0 + c4 * 4];
            As[c4 * 4 + 0][r] = a.x;
            As[c4 * 4 + 1][r] = a.y;
            As[c4 * 4 + 2][r] = a.z;
            As[c4 * 4 + 3][r] = a.w;
            float4 b = *(const float4*)&W[(size_t)(bn + r) * DMODEL + k0 + c4 * 4];
            Bs[c4 * 4 + 0][r] = b.x;
            Bs[c4 * 4 + 1][r] = b.y;
            Bs[c4 * 4 + 2][r] = b.z;
            Bs[c4 * 4 + 3][r] = b.w;
        }
        __syncthreads();

#pragma unroll
        for (int k = 0; k < 16; ++k) {
            float a[8], b[8];
            float4 a0 = *(const float4*)&As[k][ty * 8];
            float4 a1 = *(const float4*)&As[k][ty * 8 + 4];
            float4 b0 = *(const float4*)&Bs[k][tx * 8];
            float4 b1 = *(const float4*)&Bs[k][tx * 8 + 4];
            a[0]=a0.x; a[1]=a0.y; a[2]=a0.z; a[3]=a0.w;
            a[4]=a1.x; a[5]=a1.y; a[6]=a1.z; a[7]=a1.w;
            b[0]=b0.x; b[1]=b0.y; b[2]=b0.z; b[3]=b0.w;
            b[4]=b1.x; b[5]=b1.y; b[6]=b1.z; b[7]=b1.w;
#pragma unroll
            for (int i = 0; i < 8; ++i)
#pragma unroll
                for (int j = 0; j < 8; ++j)
                    acc[i][j] = fmaf(a[i], b[j], acc[i][j]);
        }
        __syncthreads();
    }

#pragma unroll
    for (int i = 0; i < 8; ++i) {
        int m = bm + ty * 8 + i;
#pragma unroll
        for (int j = 0; j < 8; ++j) {
            int n = bn + tx * 8 + j;
            if (MODE == 0) {
                int bb = m >> 11;           // m / 2048
                int s  = m & 2047;
                int hh = n >> 6;            // n / 64
                int dd = n & 63;
                Y[(((size_t)(bb * NHEADS + hh) * SEQ) + s) * DK + dd] = acc[i][j];
            } else {
                Y[(size_t)m * DMODEL + n] = acc[i][j];
            }
        }
    }
}

// ---------------------------------------------------------------------------
// Flash attention (causal), fp32.
// grid = (S/64, B*H), block = 256 threads.
// Each block: 64 query rows of one head, online softmax over k-tiles of 64.
// Output written in [B, S, H*DK] layout for the O projection.
// ---------------------------------------------------------------------------
#define TP 68   // padded tile pitch (floats)

__global__ __launch_bounds__(256)
void flash_attn_kernel(const float* __restrict__ Q,
                       const float* __restrict__ K,
                       const float* __restrict__ V,
                       float* __restrict__ Oatt)
{
    extern __shared__ float sm[];
    float* Qs = sm;               // 64*TP
    float* Ks = Qs + 64 * TP;
    float* Vs = Ks + 64 * TP;
    float* Ss = Vs + 64 * TP;

    const int bh = blockIdx.y;
    const int b  = bh >> 4;
    const int h  = bh & 15;
    const int qt = blockIdx.x;
    const int q0 = qt * 64;
    const int t  = threadIdx.x;

    const float* Qg = Q + ((size_t)(b * NHEADS + h) * SEQ + q0) * DK;
    const float* Kg = K + (size_t)(b * NHEADS + h) * SEQ * DK;
    const float* Vg = V + (size_t)(b * NHEADS + h) * SEQ * DK;

    // Load Q tile (64x64 floats), float4, coalesced
#pragma unroll
    for (int i = 0; i < 4; ++i) {
        int idx = t + i * 256;          // 0..1023
        int r = idx >> 4;
        int c = (idx & 15) * 4;
        *(float4*)&Qs[r * TP + c] = *(const float4*)&Qg[r * DK + c];
    }

    const int row  = t >> 2;            // 0..63
    const int cg   = t & 3;
    const int col0 = cg * 16;
    const int sr   = (t >> 4) * 4;      // score-tile thread mapping: 16x16 grid of 4x4
    const int sc   = (t & 15) * 4;
    const float scale = 0.125f;         // 1/sqrt(64)

    float m_old = -INFINITY;
    float l = 0.f;
    float Oa[16];
#pragma unroll
    for (int i = 0; i < 16; ++i) Oa[i] = 0.f;

    for (int kt = 0; kt <= qt; ++kt) {
        const int k0 = kt * 64;
        // Load K and V tiles
#pragma unroll
        for (int i = 0; i < 4; ++i) {
            int idx = t + i * 256;
            int r = idx >> 4;
            int c = (idx & 15) * 4;
            *(float4*)&Ks[r * TP + c] = *(const float4*)&Kg[(size_t)(k0 + r) * DK + c];
            *(float4*)&Vs[r * TP + c] = *(const float4*)&Vg[(size_t)(k0 + r) * DK + c];
        }
        __syncthreads();

        // Step A: S = Q K^T (each thread: 4x4 of the 64x64 score tile)
        float accs[4][4];
#pragma unroll
        for (int i = 0; i < 4; ++i)
#pragma unroll
            for (int j = 0; j < 4; ++j) accs[i][j] = 0.f;

#pragma unroll 8
        for (int d = 0; d < 64; ++d) {
            float qa[4], kb[4];
#pragma unroll
            for (int i = 0; i < 4; ++i) qa[i] = Qs[(sr + i) * TP + d];
#pragma unroll
            for (int j = 0; j < 4; ++j) kb[j] = Ks[(sc + j) * TP + d];
#pragma unroll
            for (int i = 0; i < 4; ++i)
#pragma unroll
                for (int j = 0; j < 4; ++j)
                    accs[i][j] = fmaf(qa[i], kb[j], accs[i][j]);
        }
#pragma unroll
        for (int i = 0; i < 4; ++i) {
            int qg = q0 + sr + i;
#pragma unroll
            for (int j = 0; j < 4; ++j) {
                int kg = k0 + sc + j;
                Ss[(sr + i) * TP + sc + j] = (kg <= qg) ? accs[i][j] * scale : -INFINITY;
            }
        }
        __syncthreads();

        // Step B: online softmax (4 threads per row, each owns 16 cols)
        float mloc = -INFINITY;
#pragma unroll
        for (int cc = 0; cc < 16; ++cc)
            mloc = fmaxf(mloc, Ss[row * TP + col0 + cc]);
        mloc = fmaxf(mloc, __shfl_xor_sync(0xffffffffu, mloc, 1));
        mloc = fmaxf(mloc, __shfl_xor_sync(0xffffffffu, mloc, 2));
        float mnew = fmaxf(m_old, mloc);
        float corr = expf(m_old - mnew);    // 0 when m_old == -inf
        l *= corr;
#pragma unroll
        for (int cc = 0; cc < 16; ++cc) Oa[cc] *= corr;

        float ps = 0.f;
#pragma unroll
        for (int cc = 0; cc < 16; ++cc) {
            float p = expf(Ss[row * TP + col0 + cc] - mnew);
            Ss[row * TP + col0 + cc] = p;
            ps += p;
        }
        ps += __shfl_xor_sync(0xffffffffu, ps, 1);
        ps += __shfl_xor_sync(0xffffffffu, ps, 2);
        l += ps;
        m_old = mnew;
        __syncthreads();   // all of P visible

        // Step C: O += P @ V (thread: row `row`, 16 cols starting at col0)
#pragma unroll 4
        for (int j = 0; j < 64; ++j) {
            float p = Ss[row * TP + j];
#pragma unroll
            for (int cc = 0; cc < 16; ++cc)
                Oa[cc] = fmaf(p, Vs[j * TP + col0 + cc], Oa[cc]);
        }
        __syncthreads();   // done reading Ss/Ks/Vs before next tile overwrites
    }

    const float inv = 1.f / l;
    float* Og = Oatt + ((size_t)(b * SEQ + q0 + row) * DMODEL) + h * DK + col0;
#pragma unroll
    for (int cc = 0; cc < 16; ++cc) Og[cc] = Oa[cc] * inv;
}

// ---------------------------------------------------------------------------
// Launch
// ---------------------------------------------------------------------------
extern "C" void kernel_launch(void* const* d_in, const int* in_sizes, int n_in,
                              void* d_out, int out_size)
{
    const float* x  = (const float*)d_in[0];
    const float* Wq = (const float*)d_in[1];
    const float* Wk = (const float*)d_in[2];
    const float* Wv = (const float*)d_in[3];
    const float* Wo = (const float*)d_in[4];
    float* out = (float*)d_out;

    float *pQ, *pK, *pV, *pATT;
    cudaGetSymbolAddress((void**)&pQ,   g_Q);
    cudaGetSymbolAddress((void**)&pK,   g_K);
    cudaGetSymbolAddress((void**)&pV,   g_V);
    cudaGetSymbolAddress((void**)&pATT, g_ATT);

    const int smem_flash = 4 * 64 * TP * sizeof(float);  // ~69.6 KB
    cudaFuncSetAttribute(flash_attn_kernel,
                         cudaFuncAttributeMaxDynamicSharedMemorySize, smem_flash);

    dim3 ggrid(DMODEL / 128, MTOT / 128);   // (8, 32)
    gemm_xwt_kernel<0><<<ggrid, 256>>>(x, Wq, pQ);
    gemm_xwt_kernel<0><<<ggrid, 256>>>(x, Wk, pK);
    gemm_xwt_kernel<0><<<ggrid, 256>>>(x, Wv, pV);

    dim3 fgrid(SEQ / 64, BATCH * NHEADS);   // (32, 32)
    flash_attn_kernel<<<fgrid, 256, smem_flash>>>(pQ, pK, pV, pATT);

    gemm_xwt_kernel<1><<<ggrid, 256>>>(pATT, Wo, out);
}

// round 4
// speedup vs baseline: 2.8612x; 2.8612x over previous
#include <cuda_runtime.h>
#include <cuda_bf16.h>
#include <cstdint>
#include <math.h>

#define BATCH   2
#define SEQ     2048
#define DMODEL  1024
#define NHEADS  16
#define DK      64
#define MTOT    (BATCH * SEQ)          // 4096

// ---------------------------------------------------------------------------
// Scratch (device globals; no allocation allowed)
// ---------------------------------------------------------------------------
__device__ __align__(16) __nv_bfloat16 g_xh[MTOT * DMODEL];
__device__ __align__(16) __nv_bfloat16 g_xl[MTOT * DMODEL];
__device__ __align__(16) __nv_bfloat16 g_wh[4][DMODEL * DMODEL];
__device__ __align__(16) __nv_bfloat16 g_wl[4][DMODEL * DMODEL];
__device__ __align__(16) float g_Q[BATCH * NHEADS * SEQ * DK];   // [B,H,S,DK]
__device__ __align__(16) float g_K[BATCH * NHEADS * SEQ * DK];
__device__ __align__(16) float g_V[BATCH * NHEADS * SEQ * DK];
__device__ __align__(16) __nv_bfloat16 g_atth[MTOT * DMODEL];    // [B,S,H*DK]
__device__ __align__(16) __nv_bfloat16 g_attl[MTOT * DMODEL];

// ---------------------------------------------------------------------------
// PTX helpers (baseline sm_80/90 features only — NO tcgen05 on this target)
// ---------------------------------------------------------------------------
__device__ __forceinline__ uint32_t smem_u32(const void* p) {
    uint32_t a;
    asm("{ .reg .u64 t; cvta.to.shared.u64 t, %1; cvt.u32.u64 %0, t; }" : "=r"(a) : "l"(p));
    return a;
}
#define CP_ASYNC16(dst, src) \
    asm volatile("cp.async.cg.shared.global [%0], [%1], 16;" :: "r"(dst), "l"(src) : "memory")
#define CP_COMMIT() asm volatile("cp.async.commit_group;" ::: "memory")
#define CP_WAIT1()  asm volatile("cp.async.wait_group 1;" ::: "memory")
#define CP_WAIT0()  asm volatile("cp.async.wait_group 0;" ::: "memory")
#define LDSM4(r0, r1, r2, r3, addr) \
    asm volatile("ldmatrix.sync.aligned.m8n8.x4.shared.b16 {%0,%1,%2,%3}, [%4];" \
        : "=r"(r0), "=r"(r1), "=r"(r2), "=r"(r3) : "r"(addr))
#define MMA16816(d, a, b0, b1) \
    asm volatile("mma.sync.aligned.m16n8k16.row.col.f32.bf16.bf16.f32 " \
        "{%0,%1,%2,%3}, {%4,%5,%6,%7}, {%8,%9}, {%0,%1,%2,%3};" \
        : "+f"((d)[0]), "+f"((d)[1]), "+f"((d)[2]), "+f"((d)[3]) \
        : "r"((a)[0]), "r"((a)[1]), "r"((a)[2]), "r"((a)[3]), "r"(b0), "r"(b1))

// ---------------------------------------------------------------------------
// fp32 -> (hi, lo) bf16 split conversion (elementwise, vectorized)
// ---------------------------------------------------------------------------
__global__ __launch_bounds__(256)
void cvt_split_kernel(const float4* __restrict__ src,
                      uint2* __restrict__ hi, uint2* __restrict__ lo, int n4)
{
    int i = blockIdx.x * blockDim.x + threadIdx.x;
    if (i >= n4) return;
    float4 v = src[i];
    __nv_bfloat162 h01 = __float22bfloat162_rn(make_float2(v.x, v.y));
    __nv_bfloat162 h23 = __float22bfloat162_rn(make_float2(v.z, v.w));
    __nv_bfloat162 l01 = __float22bfloat162_rn(make_float2(
        v.x - __bfloat162float(h01.x), v.y - __bfloat162float(h01.y)));
    __nv_bfloat162 l23 = __float22bfloat162_rn(make_float2(
        v.z - __bfloat162float(h23.x), v.w - __bfloat162float(h23.y)));
    hi[i] = make_uint2(*(uint32_t*)&h01, *(uint32_t*)&h23);
    lo[i] = make_uint2(*(uint32_t*)&l01, *(uint32_t*)&l23);
}

// ---------------------------------------------------------------------------
// Split-bf16 3-term GEMM: Y = A @ B^T, fp32 accum via mma.sync m16n8k16.
// A [M,1024] hi/lo bf16 K-major; B [1024,1024] hi/lo bf16 K-major.
// 128x128 tile/CTA, BK=32, 8 warps (2x4) of 64x32, cp.async double buffer.
// MODE 0: scatter into [B,H,S,DK];  MODE 1: plain [M,1024]
// ---------------------------------------------------------------------------
#define PITCH   80                   // smem row pitch bytes (40 bf16)
#define MATSZ   (128 * PITCH)        // 10240 B per matrix tile
#define STAGESZ (4 * MATSZ)          // Ah, Al, Bh, Bl
#define NKCH    (DMODEL / 32)        // 32 chunks

template <int MODE>
__global__ __launch_bounds__(256, 1)
void gemm_bf16_kernel(const __nv_bfloat16* __restrict__ Ah,
                      const __nv_bfloat16* __restrict__ Al,
                      const __nv_bfloat16* __restrict__ Bh,
                      const __nv_bfloat16* __restrict__ Bl,
                      float* __restrict__ Y)
{
    extern __shared__ char smem[];
    const uint32_t sbase = smem_u32(smem);
    const int t    = threadIdx.x;
    const int wid  = t >> 5;
    const int lane = t & 31;
    const int bm   = blockIdx.y * 128;
    const int bn   = blockIdx.x * 128;
    const int wm   = (wid >> 2) * 64;
    const int wn   = (wid & 3) * 32;

    // cp.async stage loader
    auto load_stage = [&](int c, int st) {
        const int k0 = c * 32;
        const uint32_t sb = sbase + st * STAGESZ;
#pragma unroll
        for (int i = 0; i < 8; ++i) {
            int idx = t + i * 256;              // 0..2047
            int mat = idx >> 9;                 // 0..3
            int r   = (idx >> 2) & 127;
            int cc  = idx & 3;
            const __nv_bfloat16* src;
            if      (mat == 0) src = Ah + (size_t)(bm + r) * DMODEL + k0 + cc * 8;
            else if (mat == 1) src = Al + (size_t)(bm + r) * DMODEL + k0 + cc * 8;
            else if (mat == 2) src = Bh + (size_t)(bn + r) * DMODEL + k0 + cc * 8;
            else               src = Bl + (size_t)(bn + r) * DMODEL + k0 + cc * 8;
            CP_ASYNC16(sb + mat * MATSZ + r * PITCH + cc * 16, src);
        }
        CP_COMMIT();
    };

    float acc[4][4][4];
#pragma unroll
    for (int i = 0; i < 4; ++i)
#pragma unroll
        for (int j = 0; j < 4; ++j)
#pragma unroll
            for (int k = 0; k < 4; ++k) acc[i][j][k] = 0.f;

    // ldmatrix lane address components
    const int a_row = lane & 15;
    const int a_kb  = (lane >> 4) * 16;
    const int b_row = ((lane >> 4) & 1) * 8 + (lane & 7);
    const int b_kb  = ((lane >> 3) & 1) * 16;

    load_stage(0, 0);

    for (int c = 0; c < NKCH; ++c) {
        if (c + 1 < NKCH) { load_stage(c + 1, (c + 1) & 1); CP_WAIT1(); }
        else              { CP_WAIT0(); }
        __syncthreads();

        const uint32_t sA = sbase + (c & 1) * STAGESZ;
        const uint32_t sB = sA + 2 * MATSZ;

#pragma unroll
        for (int kk = 0; kk < 64; kk += 32) {   // two k16 steps (bytes)
            uint32_t ah[4][4], al[4][4], bh[4][2], bl[4][2];
#pragma unroll
            for (int mt = 0; mt < 4; ++mt) {
                uint32_t ra = sA + (wm + mt * 16 + a_row) * PITCH + kk + a_kb;
                LDSM4(ah[mt][0], ah[mt][1], ah[mt][2], ah[mt][3], ra);
                LDSM4(al[mt][0], al[mt][1], al[mt][2], al[mt][3], ra + MATSZ);
            }
#pragma unroll
            for (int np = 0; np < 2; ++np) {
                uint32_t rb = sB + (wn + np * 16 + b_row) * PITCH + kk + b_kb;
                uint32_t r0, r1, r2, r3;
                LDSM4(r0, r1, r2, r3, rb);
                bh[np * 2][0] = r0; bh[np * 2][1] = r1;
                bh[np * 2 + 1][0] = r2; bh[np * 2 + 1][1] = r3;
                LDSM4(r0, r1, r2, r3, rb + MATSZ);
                bl[np * 2][0] = r0; bl[np * 2][1] = r1;
                bl[np * 2 + 1][0] = r2; bl[np * 2 + 1][1] = r3;
            }
#pragma unroll
            for (int mt = 0; mt < 4; ++mt)
#pragma unroll
                for (int nt = 0; nt < 4; ++nt) {
                    MMA16816(acc[mt][nt], ah[mt], bh[nt][0], bh[nt][1]);
                    MMA16816(acc[mt][nt], ah[mt], bl[nt][0], bl[nt][1]);
                    MMA16816(acc[mt][nt], al[mt], bh[nt][0], bh[nt][1]);
                }
        }
        __syncthreads();
    }

    // epilogue: direct fp32 stores (float2 per fragment half)
#pragma unroll
    for (int mt = 0; mt < 4; ++mt) {
#pragma unroll
        for (int nt = 0; nt < 4; ++nt) {
            int m0 = bm + wm + mt * 16 + (lane >> 2);
            int n0 = bn + wn + nt * 8 + 2 * (lane & 3);
#pragma unroll
            for (int hhalf = 0; hhalf < 2; ++hhalf) {
                int m = m0 + hhalf * 8;
                float2 v = make_float2(acc[mt][nt][hhalf * 2], acc[mt][nt][hhalf * 2 + 1]);
                if (MODE == 0) {
                    int bb = m >> 11, s = m & 2047, hh = n0 >> 6, dd = n0 & 63;
                    *(float2*)&Y[(((size_t)(bb * NHEADS + hh) * SEQ) + s) * DK + dd] = v;
                } else {
                    *(float2*)&Y[(size_t)m * DMODEL + n0] = v;
                }
            }
        }
    }
}

// ---------------------------------------------------------------------------
// Flash attention (causal, fp32) — conflict-free strided tiles + FMA exp2.
// Writes ATT output directly as hi/lo bf16 for the O projection.
// ---------------------------------------------------------------------------
#define FP 68   // smem pitch (floats)

__device__ __forceinline__ float fexp2(float t) {
    t = fmaxf(t, -126.f);
    float r = rintf(t);
    float f = t - r;
    float p =            0.0013333558f;
    p = fmaf(p, f, 0.0096181291f);
    p = fmaf(p, f, 0.0555041087f);
    p = fmaf(p, f, 0.2402265069f);
    p = fmaf(p, f, 0.6931471806f);
    p = fmaf(p, f, 1.0f);
    return p * __int_as_float(((int)r + 127) << 23);
}

__global__ __launch_bounds__(256)
void flash_attn_kernel(const float* __restrict__ Q,
                       const float* __restrict__ K,
                       const float* __restrict__ V,
                       __nv_bfloat16* __restrict__ Oh,
                       __nv_bfloat16* __restrict__ Ol)
{
    extern __shared__ float sm[];
    float* Qs = sm;               // 64*FP
    float* Ks = Qs + 64 * FP;
    float* Vs = Ks + 64 * FP;
    float* Ss = Vs + 64 * FP;

    const int bh = blockIdx.y;
    const int b  = bh >> 4;
    const int h  = bh & 15;
    const int qt = blockIdx.x;
    const int q0 = qt * 64;
    const int t  = threadIdx.x;

    const float* Qg = Q + ((size_t)(b * NHEADS + h) * SEQ + q0) * DK;
    const float* Kg = K + (size_t)(b * NHEADS + h) * SEQ * DK;
    const float* Vg = V + (size_t)(b * NHEADS + h) * SEQ * DK;

#pragma unroll
    for (int i = 0; i < 4; ++i) {
        int idx = t + i * 256;
        int r = idx >> 4;
        int c = (idx & 15) * 4;
        *(float4*)&Qs[r * FP + c] = *(const float4*)&Qg[r * DK + c];
    }

    const int rq   = t >> 4;            // q rows: rq + 16i
    const int ck   = t & 15;            // k rows: ck + 16j (step A)
    const int dcol = (t & 15) * 4;      // O cols (step C)
    const float scale = 0.125f;
    const float L2E = 1.4426950408889634f;

    float m_s[4], l_s[4], Oa[4][4];
#pragma unroll
    for (int i = 0; i < 4; ++i) {
        m_s[i] = -INFINITY; l_s[i] = 0.f;
#pragma unroll
        for (int j = 0; j < 4; ++j) Oa[i][j] = 0.f;
    }

    for (int kt = 0; kt <= qt; ++kt) {
        const int k0 = kt * 64;
#pragma unroll
        for (int i = 0; i < 4; ++i) {
            int idx = t + i * 256;
            int r = idx >> 4;
            int c = (idx & 15) * 4;
            *(float4*)&Ks[r * FP + c] = *(const float4*)&Kg[(size_t)(k0 + r) * DK + c];
            *(float4*)&Vs[r * FP + c] = *(const float4*)&Vg[(size_t)(k0 + r) * DK + c];
        }
        __syncthreads();

        float accs[4][4];
#pragma unroll
        for (int i = 0; i < 4; ++i)
#pragma unroll
            for (int j = 0; j < 4; ++j) accs[i][j] = 0.f;

#pragma unroll
        for (int d0 = 0; d0 < 64; d0 += 4) {
            float4 qv[4], kv[4];
#pragma unroll
            for (int i = 0; i < 4; ++i) qv[i] = *(const float4*)&Qs[(rq + 16 * i) * FP + d0];
#pragma unroll
            for (int j = 0; j < 4; ++j) kv[j] = *(const float4*)&Ks[(ck + 16 * j) * FP + d0];
#pragma unroll
            for (int i = 0; i < 4; ++i)
#pragma unroll
                for (int j = 0; j < 4; ++j) {
                    accs[i][j] = fmaf(qv[i].x, kv[j].x, accs[i][j]);
                    accs[i][j] = fmaf(qv[i].y, kv[j].y, accs[i][j]);
                    accs[i][j] = fmaf(qv[i].z, kv[j].z, accs[i][j]);
                    accs[i][j] = fmaf(qv[i].w, kv[j].w, accs[i][j]);
                }
        }

        if (kt == qt) {
#pragma unroll
            for (int i = 0; i < 4; ++i) {
                int qg = rq + 16 * i;
#pragma unroll
                for (int j = 0; j < 4; ++j) {
                    int kg = ck + 16 * j;
                    accs[i][j] = (kg <= qg) ? accs[i][j] * scale : -INFINITY;
                }
            }
        } else {
#pragma unroll
            for (int i = 0; i < 4; ++i)
#pragma unroll
                for (int j = 0; j < 4; ++j) accs[i][j] *= scale;
        }

#pragma unroll
        for (int i = 0; i < 4; ++i) {
            float rm = fmaxf(fmaxf(accs[i][0], accs[i][1]), fmaxf(accs[i][2], accs[i][3]));
            rm = fmaxf(rm, __shfl_xor_sync(0xffffffffu, rm, 1));
            rm = fmaxf(rm, __shfl_xor_sync(0xffffffffu, rm, 2));
            rm = fmaxf(rm, __shfl_xor_sync(0xffffffffu, rm, 4));
            rm = fmaxf(rm, __shfl_xor_sync(0xffffffffu, rm, 8));
            float mnew = fmaxf(m_s[i], rm);
            float corr = fexp2((m_s[i] - mnew) * L2E);
            l_s[i] *= corr;
#pragma unroll
            for (int j = 0; j < 4; ++j) Oa[i][j] *= corr;
            m_s[i] = mnew;

            float ps = 0.f;
#pragma unroll
            for (int j = 0; j < 4; ++j) {
                float p = fexp2((accs[i][j] - mnew) * L2E);
                Ss[(rq + 16 * i) * FP + ck + 16 * j] = p;
                ps += p;
            }
            ps += __shfl_xor_sync(0xffffffffu, ps, 1);
            ps += __shfl_xor_sync(0xffffffffu, ps, 2);
            ps += __shfl_xor_sync(0xffffffffu, ps, 4);
            ps += __shfl_xor_sync(0xffffffffu, ps, 8);
            l_s[i] += ps;
        }
        __syncthreads();

#pragma unroll 8
        for (int k = 0; k < 64; ++k) {
            float4 vv = *(const float4*)&Vs[k * FP + dcol];
#pragma unroll
            for (int i = 0; i < 4; ++i) {
                float p = Ss[(rq + 16 * i) * FP + k];
                Oa[i][0] = fmaf(p, vv.x, Oa[i][0]);
                Oa[i][1] = fmaf(p, vv.y, Oa[i][1]);
                Oa[i][2] = fmaf(p, vv.z, Oa[i][2]);
                Oa[i][3] = fmaf(p, vv.w, Oa[i][3]);
            }
        }
        __syncthreads();
    }

#pragma unroll
    for (int i = 0; i < 4; ++i) {
        float inv = 1.f / l_s[i];
        float v0 = Oa[i][0] * inv, v1 = Oa[i][1] * inv;
        float v2 = Oa[i][2] * inv, v3 = Oa[i][3] * inv;
        __nv_bfloat162 h01 = __float22bfloat162_rn(make_float2(v0, v1));
        __nv_bfloat162 h23 = __float22bfloat162_rn(make_float2(v2, v3));
        __nv_bfloat162 l01 = __float22bfloat162_rn(make_float2(
            v0 - __bfloat162float(h01.x), v1 - __bfloat162float(h01.y)));
        __nv_bfloat162 l23 = __float22bfloat162_rn(make_float2(
            v2 - __bfloat162float(h23.x), v3 - __bfloat162float(h23.y)));
        size_t off = ((size_t)(b * SEQ + q0 + rq + 16 * i) * DMODEL) + h * DK + dcol;
        *(uint2*)&Oh[off] = make_uint2(*(uint32_t*)&h01, *(uint32_t*)&h23);
        *(uint2*)&Ol[off] = make_uint2(*(uint32_t*)&l01, *(uint32_t*)&l23);
    }
}

// ---------------------------------------------------------------------------
// Launch
// ---------------------------------------------------------------------------
extern "C" void kernel_launch(void* const* d_in, const int* in_sizes, int n_in,
                              void* d_out, int out_size)
{
    const float* x = (const float*)d_in[0];
    const float* W[4] = { (const float*)d_in[1], (const float*)d_in[2],
                          (const float*)d_in[3], (const float*)d_in[4] };
    float* out = (float*)d_out;

    __nv_bfloat16 *xh, *xl, *wh, *wl, *atth, *attl;
    float *pQ, *pK, *pV;
    cudaGetSymbolAddress((void**)&xh, g_xh);
    cudaGetSymbolAddress((void**)&xl, g_xl);
    cudaGetSymbolAddress((void**)&wh, g_wh);
    cudaGetSymbolAddress((void**)&wl, g_wl);
    cudaGetSymbolAddress((void**)&pQ, g_Q);
    cudaGetSymbolAddress((void**)&pK, g_K);
    cudaGetSymbolAddress((void**)&pV, g_V);
    cudaGetSymbolAddress((void**)&atth, g_atth);
    cudaGetSymbolAddress((void**)&attl, g_attl);

    const int smem_gemm = 2 * STAGESZ;                   // 81920 B
    cudaFuncSetAttribute(gemm_bf16_kernel<0>, cudaFuncAttributeMaxDynamicSharedMemorySize, smem_gemm);
    cudaFuncSetAttribute(gemm_bf16_kernel<1>, cudaFuncAttributeMaxDynamicSharedMemorySize, smem_gemm);
    const int smem_flash = 4 * 64 * FP * sizeof(float);  // ~69.6 KB
    cudaFuncSetAttribute(flash_attn_kernel, cudaFuncAttributeMaxDynamicSharedMemorySize, smem_flash);

    // 1. split-convert inputs to hi/lo bf16
    int n4x = MTOT * DMODEL / 4;
    cvt_split_kernel<<<(n4x + 255) / 256, 256>>>((const float4*)x, (uint2*)xh, (uint2*)xl, n4x);
    int n4w = DMODEL * DMODEL / 4;
    for (int i = 0; i < 4; ++i)
        cvt_split_kernel<<<(n4w + 255) / 256, 256>>>((const float4*)W[i],
            (uint2*)(wh + (size_t)i * DMODEL * DMODEL),
            (uint2*)(wl + (size_t)i * DMODEL * DMODEL), n4w);

    // 2. Q/K/V projections (tensor core)
    dim3 ggrid(DMODEL / 128, MTOT / 128);   // (8, 32)
    gemm_bf16_kernel<0><<<ggrid, 256, smem_gemm>>>(xh, xl, wh + 0 * (size_t)DMODEL * DMODEL, wl + 0 * (size_t)DMODEL * DMODEL, pQ);
    gemm_bf16_kernel<0><<<ggrid, 256, smem_gemm>>>(xh, xl, wh + 1 * (size_t)DMODEL * DMODEL, wl + 1 * (size_t)DMODEL * DMODEL, pK);
    gemm_bf16_kernel<0><<<ggrid, 256, smem_gemm>>>(xh, xl, wh + 2 * (size_t)DMODEL * DMODEL, wl + 2 * (size_t)DMODEL * DMODEL, pV);

    // 3. attention
    dim3 fgrid(SEQ / 64, BATCH * NHEADS);   // (32, 32)
    flash_attn_kernel<<<fgrid, 256, smem_flash>>>(pQ, pK, pV, atth, attl);

    // 4. output projection
    gemm_bf16_kernel<1><<<ggrid, 256, smem_gemm>>>(atth, attl, wh + 3 * (size_t)DMODEL * DMODEL, wl + 3 * (size_t)DMODEL * DMODEL, out);
}

// round 6
// speedup vs baseline: 4.7252x; 1.6515x over previous
#include <cuda_runtime.h>
#include <cuda_bf16.h>
#include <cstdint>
#include <math.h>

#define BATCH   2
#define SEQ     2048
#define DMODEL  1024
#define NHEADS  16
#define DK      64
#define MTOT    (BATCH * SEQ)          // 4096
#define DD      (DMODEL * DMODEL)

// ---------------------------------------------------------------------------
// Scratch (device globals; no allocation allowed)
// ---------------------------------------------------------------------------
__device__ __align__(16) __nv_bfloat16 g_xh[MTOT * DMODEL];
__device__ __align__(16) __nv_bfloat16 g_xl[MTOT * DMODEL];
__device__ __align__(16) __nv_bfloat16 g_wh[4][DD];
__device__ __align__(16) __nv_bfloat16 g_wl[4][DD];
__device__ __align__(16) __nv_bfloat16 g_qh[BATCH * NHEADS * SEQ * DK];  // [B,H,S,DK]
__device__ __align__(16) __nv_bfloat16 g_ql[BATCH * NHEADS * SEQ * DK];
__device__ __align__(16) __nv_bfloat16 g_kh[BATCH * NHEADS * SEQ * DK];
__device__ __align__(16) __nv_bfloat16 g_kl[BATCH * NHEADS * SEQ * DK];
__device__ __align__(16) __nv_bfloat16 g_vh[BATCH * NHEADS * SEQ * DK];
__device__ __align__(16) __nv_bfloat16 g_vl[BATCH * NHEADS * SEQ * DK];
__device__ __align__(16) __nv_bfloat16 g_atth[MTOT * DMODEL];            // [B,S,H*DK]
__device__ __align__(16) __nv_bfloat16 g_attl[MTOT * DMODEL];

// ---------------------------------------------------------------------------
// PTX helpers (baseline sm_80/90 features only)
// ---------------------------------------------------------------------------
__device__ __forceinline__ uint32_t smem_u32(const void* p) {
    uint32_t a;
    asm("{ .reg .u64 t; cvta.to.shared.u64 t, %1; cvt.u32.u64 %0, t; }" : "=r"(a) : "l"(p));
    return a;
}
#define CP_ASYNC16(dst, src) \
    asm volatile("cp.async.cg.shared.global [%0], [%1], 16;" :: "r"(dst), "l"(src) : "memory")
#define CP_COMMIT() asm volatile("cp.async.commit_group;" ::: "memory")
#define CP_WAIT1()  asm volatile("cp.async.wait_group 1;" ::: "memory")
#define CP_WAIT0()  asm volatile("cp.async.wait_group 0;" ::: "memory")
#define LDSM4(r0, r1, r2, r3, addr) \
    asm volatile("ldmatrix.sync.aligned.m8n8.x4.shared.b16 {%0,%1,%2,%3}, [%4];" \
        : "=r"(r0), "=r"(r1), "=r"(r2), "=r"(r3) : "r"(addr))
#define LDSM4T(r0, r1, r2, r3, addr) \
    asm volatile("ldmatrix.sync.aligned.m8n8.x4.trans.shared.b16 {%0,%1,%2,%3}, [%4];" \
        : "=r"(r0), "=r"(r1), "=r"(r2), "=r"(r3) : "r"(addr))
#define MMA16816(d, a, b0, b1) \
    asm volatile("mma.sync.aligned.m16n8k16.row.col.f32.bf16.bf16.f32 " \
        "{%0,%1,%2,%3}, {%4,%5,%6,%7}, {%8,%9}, {%0,%1,%2,%3};" \
        : "+f"((d)[0]), "+f"((d)[1]), "+f"((d)[2]), "+f"((d)[3]) \
        : "r"((a)[0]), "r"((a)[1]), "r"((a)[2]), "r"((a)[3]), "r"(b0), "r"(b1))

__device__ __forceinline__ uint32_t pack_bf16_hi(float x, float y) {
    __nv_bfloat162 h = __float22bfloat162_rn(make_float2(x, y));
    return *(uint32_t*)&h;
}
__device__ __forceinline__ uint32_t pack_bf16_lo(float x, float y, uint32_t hi) {
    __nv_bfloat162 h = *(__nv_bfloat162*)&hi;
    __nv_bfloat162 l = __float22bfloat162_rn(make_float2(
        x - __bfloat162float(h.x), y - __bfloat162float(h.y)));
    return *(uint32_t*)&l;
}

// ---------------------------------------------------------------------------
// fp32 -> (hi, lo) bf16 split conversion (elementwise, vectorized)
// ---------------------------------------------------------------------------
__global__ __launch_bounds__(256)
void cvt_split_kernel(const float4* __restrict__ src,
                      uint2* __restrict__ hi, uint2* __restrict__ lo, int n4)
{
    int i = blockIdx.x * blockDim.x + threadIdx.x;
    if (i >= n4) return;
    float4 v = src[i];
    uint32_t h01 = pack_bf16_hi(v.x, v.y);
    uint32_t h23 = pack_bf16_hi(v.z, v.w);
    uint32_t l01 = pack_bf16_lo(v.x, v.y, h01);
    uint32_t l23 = pack_bf16_lo(v.z, v.w, h23);
    hi[i] = make_uint2(h01, h23);
    lo[i] = make_uint2(l01, l23);
}

// ---------------------------------------------------------------------------
// Split-bf16 3-term GEMM core (128x128 tile/CTA, BK=32, 8 warps of 64x32)
// ---------------------------------------------------------------------------
#define PITCH   80                   // smem row pitch bytes (40 bf16)
#define MATSZ   (128 * PITCH)        // 10240 B per matrix tile
#define STAGESZ (4 * MATSZ)          // Ah, Al, Bh, Bl
#define NKCH    (DMODEL / 32)        // 32 chunks

template <typename Epi>
__device__ __forceinline__
void gemm_core(const __nv_bfloat16* Ah, const __nv_bfloat16* Al,
               const __nv_bfloat16* Bh, const __nv_bfloat16* Bl,
               int bm, int bn, Epi epi)
{
    extern __shared__ char smem[];
    const uint32_t sbase = smem_u32(smem);
    const int t    = threadIdx.x;
    const int wid  = t >> 5;
    const int lane = t & 31;
    const int wm   = (wid >> 2) * 64;
    const int wn   = (wid & 3) * 32;

    auto load_stage = [&](int c, int st) {
        const int k0 = c * 32;
        const uint32_t sb = sbase + st * STAGESZ;
#pragma unroll
        for (int i = 0; i < 8; ++i) {
            int idx = t + i * 256;
            int mat = idx >> 9;
            int r   = (idx >> 2) & 127;
            int cc  = idx & 3;
            const __nv_bfloat16* src;
            if      (mat == 0) src = Ah + (size_t)(bm + r) * DMODEL + k0 + cc * 8;
            else if (mat == 1) src = Al + (size_t)(bm + r) * DMODEL + k0 + cc * 8;
            else if (mat == 2) src = Bh + (size_t)(bn + r) * DMODEL + k0 + cc * 8;
            else               src = Bl + (size_t)(bn + r) * DMODEL + k0 + cc * 8;
            CP_ASYNC16(sb + mat * MATSZ + r * PITCH + cc * 16, src);
        }
        CP_COMMIT();
    };

    float acc[4][4][4];
#pragma unroll
    for (int i = 0; i < 4; ++i)
#pragma unroll
        for (int j = 0; j < 4; ++j)
#pragma unroll
            for (int k = 0; k < 4; ++k) acc[i][j][k] = 0.f;

    const int a_row = lane & 15;
    const int a_kb  = (lane >> 4) * 16;
    const int b_row = ((lane >> 4) & 1) * 8 + (lane & 7);
    const int b_kb  = ((lane >> 3) & 1) * 16;

    load_stage(0, 0);

    for (int c = 0; c < NKCH; ++c) {
        if (c + 1 < NKCH) { load_stage(c + 1, (c + 1) & 1); CP_WAIT1(); }
        else              { CP_WAIT0(); }
        __syncthreads();

        const uint32_t sA = sbase + (c & 1) * STAGESZ;
        const uint32_t sB = sA + 2 * MATSZ;

#pragma unroll
        for (int kk = 0; kk < 64; kk += 32) {
            uint32_t ah[4][4], al[4][4], bh[4][2], bl[4][2];
#pragma unroll
            for (int mt = 0; mt < 4; ++mt) {
                uint32_t ra = sA + (wm + mt * 16 + a_row) * PITCH + kk + a_kb;
                LDSM4(ah[mt][0], ah[mt][1], ah[mt][2], ah[mt][3], ra);
                LDSM4(al[mt][0], al[mt][1], al[mt][2], al[mt][3], ra + MATSZ);
            }
#pragma unroll
            for (int np = 0; np < 2; ++np) {
                uint32_t rb = sB + (wn + np * 16 + b_row) * PITCH + kk + b_kb;
                uint32_t r0, r1, r2, r3;
                LDSM4(r0, r1, r2, r3, rb);
                bh[np * 2][0] = r0; bh[np * 2][1] = r1;
                bh[np * 2 + 1][0] = r2; bh[np * 2 + 1][1] = r3;
                LDSM4(r0, r1, r2, r3, rb + MATSZ);
                bl[np * 2][0] = r0; bl[np * 2][1] = r1;
                bl[np * 2 + 1][0] = r2; bl[np * 2 + 1][1] = r3;
            }
#pragma unroll
            for (int mt = 0; mt < 4; ++mt)
#pragma unroll
                for (int nt = 0; nt < 4; ++nt) {
                    MMA16816(acc[mt][nt], ah[mt], bh[nt][0], bh[nt][1]);
                    MMA16816(acc[mt][nt], ah[mt], bl[nt][0], bl[nt][1]);
                    MMA16816(acc[mt][nt], al[mt], bh[nt][0], bh[nt][1]);
                }
        }
        __syncthreads();
    }

    // epilogue callback per float2 fragment
#pragma unroll
    for (int mt = 0; mt < 4; ++mt)
#pragma unroll
        for (int nt = 0; nt < 4; ++nt) {
            int m0 = bm + wm + mt * 16 + (lane >> 2);
            int n0 = bn + wn + nt * 8 + 2 * (lane & 3);
#pragma unroll
            for (int hhalf = 0; hhalf < 2; ++hhalf)
                epi(m0 + hhalf * 8, n0, acc[mt][nt][hhalf * 2], acc[mt][nt][hhalf * 2 + 1]);
        }
}

// Fused Q/K/V projection: z selects weight + destination; out hi/lo bf16 [B,H,S,DK]
__global__ __launch_bounds__(256, 1)
void gemm_qkv_kernel(const __nv_bfloat16* __restrict__ xh,
                     const __nv_bfloat16* __restrict__ xl,
                     const __nv_bfloat16* __restrict__ wh,
                     const __nv_bfloat16* __restrict__ wl,
                     __nv_bfloat16* __restrict__ qh, __nv_bfloat16* __restrict__ ql,
                     __nv_bfloat16* __restrict__ kh, __nv_bfloat16* __restrict__ kl,
                     __nv_bfloat16* __restrict__ vh, __nv_bfloat16* __restrict__ vl)
{
    const int z = blockIdx.z;
    const __nv_bfloat16* Bh = wh + (size_t)z * DD;
    const __nv_bfloat16* Bl = wl + (size_t)z * DD;
    __nv_bfloat16* Yh = (z == 0) ? qh : (z == 1) ? kh : vh;
    __nv_bfloat16* Yl = (z == 0) ? ql : (z == 1) ? kl : vl;
    const float scale = (z == 0) ? 0.125f : 1.0f;   // fold 1/sqrt(dk) into Q (exact)

    gemm_core(xh, xl, Bh, Bl, blockIdx.y * 128, blockIdx.x * 128,
        [&](int m, int n, float v0, float v1) {
            v0 *= scale; v1 *= scale;
            uint32_t hp = pack_bf16_hi(v0, v1);
            uint32_t lp = pack_bf16_lo(v0, v1, hp);
            int bb = m >> 11, s = m & 2047, hh = n >> 6, dd = n & 63;
            size_t off = (((size_t)(bb * NHEADS + hh) * SEQ) + s) * DK + dd;
            *(uint32_t*)&Yh[off] = hp;
            *(uint32_t*)&Yl[off] = lp;
        });
}

// Output projection: fp32 result
__global__ __launch_bounds__(256, 1)
void gemm_out_kernel(const __nv_bfloat16* __restrict__ ah,
                     const __nv_bfloat16* __restrict__ al,
                     const __nv_bfloat16* __restrict__ bh,
                     const __nv_bfloat16* __restrict__ bl,
                     float* __restrict__ Y)
{
    gemm_core(ah, al, bh, bl, blockIdx.y * 128, blockIdx.x * 128,
        [&](int m, int n, float v0, float v1) {
            *(float2*)&Y[(size_t)m * DMODEL + n] = make_float2(v0, v1);
        });
}

// ---------------------------------------------------------------------------
// Tensor-core flash attention (causal).
// CTA: 128 q-rows of one head; 8 warps x 16 rows. K/V tiles of 64 keys,
// double-buffered cp.async. 3-term split MMA for scores and P.V.
// ---------------------------------------------------------------------------
#define ROWB   144                    // smem row pitch bytes (72 bf16)
#define FQ_SZ  (128 * ROWB)           // 18432 per Q matrix
#define FKV_SZ (64 * ROWB)            // 9216 per K/V matrix
#define FSTAGE (4 * FKV_SZ)           // KH, KL, VH, VL
#define FSMEM  (2 * FQ_SZ + 2 * FSTAGE)  // 110592

__device__ __forceinline__ float fexp2(float t) {
    t = fmaxf(t, -126.f);
    float r = rintf(t);
    float f = t - r;
    float p =            0.0013333558f;
    p = fmaf(p, f, 0.0096181291f);
    p = fmaf(p, f, 0.0555041087f);
    p = fmaf(p, f, 0.2402265069f);
    p = fmaf(p, f, 0.6931471806f);
    p = fmaf(p, f, 1.0f);
    return p * __int_as_float(((int)r + 127) << 23);
}

__global__ __launch_bounds__(256, 1)
void flash_tc_kernel(const __nv_bfloat16* __restrict__ Qh,
                     const __nv_bfloat16* __restrict__ Ql,
                     const __nv_bfloat16* __restrict__ Kh,
                     const __nv_bfloat16* __restrict__ Kl,
                     const __nv_bfloat16* __restrict__ Vh,
                     const __nv_bfloat16* __restrict__ Vl,
                     __nv_bfloat16* __restrict__ Oh,
                     __nv_bfloat16* __restrict__ Ol)
{
    extern __shared__ char smem[];
    const uint32_t sbase = smem_u32(smem);
    const int t    = threadIdx.x;
    const int wid  = t >> 5;
    const int lane = t & 31;
    const int bh   = blockIdx.y;
    const int b    = bh >> 4;
    const int h    = bh & 15;
    const int qt   = gridDim.x - 1 - blockIdx.x;   // long CTAs first
    const int q0   = qt * 128;
    const int wm   = wid * 16;
    const int ntiles = 2 * qt + 2;

    const size_t headoff = (size_t)(b * NHEADS + h) * SEQ * DK;

    // --- preamble: load Q (hi+lo) then stage 0 of K/V ---
    {
#pragma unroll
        for (int i = 0; i < 8; ++i) {
            int idx = t + i * 256;              // 0..2047
            int arr = idx >> 10;                // 0=hi 1=lo
            int c   = idx & 1023;
            int r   = c >> 3;
            int ch  = c & 7;
            const __nv_bfloat16* src = (arr ? Ql : Qh) + headoff + (size_t)(q0 + r) * DK + ch * 8;
            CP_ASYNC16(sbase + arr * FQ_SZ + r * ROWB + ch * 16, src);
        }
        CP_COMMIT();
    }
    auto load_kv = [&](int kt, int st) {
        const int k0 = kt * 64;
        const uint32_t sb = sbase + 2 * FQ_SZ + st * FSTAGE;
#pragma unroll
        for (int i = 0; i < 8; ++i) {
            int idx = t + i * 256;              // 0..2047
            int arr = idx >> 9;                 // 0=KH 1=KL 2=VH 3=VL
            int c   = idx & 511;
            int r   = c >> 3;
            int ch  = c & 7;
            const __nv_bfloat16* base = (arr == 0) ? Kh : (arr == 1) ? Kl : (arr == 2) ? Vh : Vl;
            const __nv_bfloat16* src = base + headoff + (size_t)(k0 + r) * DK + ch * 8;
            CP_ASYNC16(sb + arr * FKV_SZ + r * ROWB + ch * 16, src);
        }
        CP_COMMIT();
    };
    load_kv(0, 0);

    CP_WAIT1();          // Q done (stage 0 may still be in flight)
    __syncthreads();

    // --- preload Q fragments (4 k-steps over dk=64) ---
    uint32_t qfh[4][4], qfl[4][4];
    {
        const int a_row = lane & 15;
        const int a_kb  = (lane >> 4) * 16;
#pragma unroll
        for (int kk = 0; kk < 4; ++kk) {
            uint32_t ra = sbase + (wm + a_row) * ROWB + kk * 32 + a_kb;
            LDSM4(qfh[kk][0], qfh[kk][1], qfh[kk][2], qfh[kk][3], ra);
            LDSM4(qfl[kk][0], qfl[kk][1], qfl[kk][2], qfl[kk][3], ra + FQ_SZ);
        }
    }

    const int b_row = ((lane >> 4) & 1) * 8 + (lane & 7);
    const int b_kb  = ((lane >> 3) & 1) * 16;
    const int vrow  = lane & 15;
    const int vcb   = (lane >> 4) * 8;
    const float L2E = 1.4426950408889634f;

    float o[8][4];
#pragma unroll
    for (int i = 0; i < 8; ++i)
#pragma unroll
        for (int j = 0; j < 4; ++j) o[i][j] = 0.f;
    float m_s[2] = {-INFINITY, -INFINITY};
    float l_s[2] = {0.f, 0.f};

    for (int kt = 0; kt < ntiles; ++kt) {
        CP_WAIT0();
        __syncthreads();
        if (kt + 1 < ntiles) load_kv(kt + 1, (kt + 1) & 1);

        const uint32_t stg = sbase + 2 * FQ_SZ + (kt & 1) * FSTAGE;
        const int k0 = kt * 64;

        // ---- scores: S = Q K^T (3-term), 8 n8-tiles per warp ----
        float s[8][4];
#pragma unroll
        for (int i = 0; i < 8; ++i)
#pragma unroll
            for (int j = 0; j < 4; ++j) s[i][j] = 0.f;

#pragma unroll
        for (int kk = 0; kk < 4; ++kk) {
#pragma unroll
            for (int nt2 = 0; nt2 < 4; ++nt2) {
                uint32_t addr = stg + (nt2 * 16 + b_row) * ROWB + kk * 32 + b_kb;
                uint32_t h0, h1, h2, h3, l0, l1, l2, l3;
                LDSM4(h0, h1, h2, h3, addr);            // KH
                LDSM4(l0, l1, l2, l3, addr + FKV_SZ);   // KL
                MMA16816(s[nt2 * 2],     qfh[kk], h0, h1);
                MMA16816(s[nt2 * 2 + 1], qfh[kk], h2, h3);
                MMA16816(s[nt2 * 2],     qfh[kk], l0, l1);
                MMA16816(s[nt2 * 2 + 1], qfh[kk], l2, l3);
                MMA16816(s[nt2 * 2],     qfl[kk], h0, h1);
                MMA16816(s[nt2 * 2 + 1], qfl[kk], h2, h3);
            }
        }

        // ---- causal mask (scale already folded into Q) ----
        if (k0 + 63 > q0 + wm) {
#pragma unroll
            for (int nt = 0; nt < 8; ++nt)
#pragma unroll
                for (int c = 0; c < 4; ++c) {
                    int col = k0 + nt * 8 + 2 * (lane & 3) + (c & 1);
                    int row = q0 + wm + (lane >> 2) + (c >> 1) * 8;
                    if (col > row) s[nt][c] = -INFINITY;
                }
        }

        // ---- online softmax (per accumulator row r=0,1) ----
#pragma unroll
        for (int r = 0; r < 2; ++r) {
            float rm = -INFINITY;
#pragma unroll
            for (int nt = 0; nt < 8; ++nt)
                rm = fmaxf(rm, fmaxf(s[nt][r * 2], s[nt][r * 2 + 1]));
            rm = fmaxf(rm, __shfl_xor_sync(0xffffffffu, rm, 1));
            rm = fmaxf(rm, __shfl_xor_sync(0xffffffffu, rm, 2));
            float mnew = fmaxf(m_s[r], rm);
            float corr = fexp2((m_s[r] - mnew) * L2E);
            l_s[r] *= corr;
#pragma unroll
            for (int dn = 0; dn < 8; ++dn) {
                o[dn][r * 2]     *= corr;
                o[dn][r * 2 + 1] *= corr;
            }
            m_s[r] = mnew;
            float ps = 0.f;
#pragma unroll
            for (int nt = 0; nt < 8; ++nt) {
                float p0 = fexp2((s[nt][r * 2]     - mnew) * L2E);
                float p1 = fexp2((s[nt][r * 2 + 1] - mnew) * L2E);
                s[nt][r * 2] = p0; s[nt][r * 2 + 1] = p1;
                ps += p0 + p1;
            }
            ps += __shfl_xor_sync(0xffffffffu, ps, 1);
            ps += __shfl_xor_sync(0xffffffffu, ps, 2);
            l_s[r] += ps;
        }

        // ---- O += P @ V (3-term), k-dim = keys ----
#pragma unroll
        for (int kk = 0; kk < 4; ++kk) {
            const int t0 = 2 * kk, t1 = 2 * kk + 1;
            uint32_t pah[4], pal[4];
            pah[0] = pack_bf16_hi(s[t0][0], s[t0][1]);
            pah[1] = pack_bf16_hi(s[t0][2], s[t0][3]);
            pah[2] = pack_bf16_hi(s[t1][0], s[t1][1]);
            pah[3] = pack_bf16_hi(s[t1][2], s[t1][3]);
            pal[0] = pack_bf16_lo(s[t0][0], s[t0][1], pah[0]);
            pal[1] = pack_bf16_lo(s[t0][2], s[t0][3], pah[1]);
            pal[2] = pack_bf16_lo(s[t1][0], s[t1][1], pah[2]);
            pal[3] = pack_bf16_lo(s[t1][2], s[t1][3], pah[3]);
#pragma unroll
            for (int dp = 0; dp < 4; ++dp) {
                uint32_t vaddr = stg + 2 * FKV_SZ + (kk * 16 + vrow) * ROWB + (dp * 16 + vcb) * 2;
                uint32_t v0, v1, v2, v3;
                LDSM4T(v0, v1, v2, v3, vaddr);            // VH
                MMA16816(o[dp * 2],     pah, v0, v1);
                MMA16816(o[dp * 2 + 1], pah, v2, v3);
                MMA16816(o[dp * 2],     pal, v0, v1);
                MMA16816(o[dp * 2 + 1], pal, v2, v3);
                LDSM4T(v0, v1, v2, v3, vaddr + FKV_SZ);   // VL
                MMA16816(o[dp * 2],     pah, v0, v1);
                MMA16816(o[dp * 2 + 1], pah, v2, v3);
            }
        }
    }

    // ---- normalize + split-store to ATT [B,S,H*DK] ----
    const float inv0 = 1.f / l_s[0];
    const float inv1 = 1.f / l_s[1];
    const int row0 = q0 + wm + (lane >> 2);
    const int colb = h * DK + 2 * (lane & 3);
#pragma unroll
    for (int dn = 0; dn < 8; ++dn) {
        int col = colb + dn * 8;
        {
            float v0 = o[dn][0] * inv0, v1 = o[dn][1] * inv0;
            uint32_t hp = pack_bf16_hi(v0, v1);
            uint32_t lp = pack_bf16_lo(v0, v1, hp);
            size_t off = (size_t)(b * SEQ + row0) * DMODEL + col;
            *(uint32_t*)&Oh[off] = hp;
            *(uint32_t*)&Ol[off] = lp;
        }
        {
            float v0 = o[dn][2] * inv1, v1 = o[dn][3] * inv1;
            uint32_t hp = pack_bf16_hi(v0, v1);
            uint32_t lp = pack_bf16_lo(v0, v1, hp);
            size_t off = (size_t)(b * SEQ + row0 + 8) * DMODEL + col;
            *(uint32_t*)&Oh[off] = hp;
            *(uint32_t*)&Ol[off] = lp;
        }
    }
}

// ---------------------------------------------------------------------------
// Launch
// ---------------------------------------------------------------------------
extern "C" void kernel_launch(void* const* d_in, const int* in_sizes, int n_in,
                              void* d_out, int out_size)
{
    const float* x = (const float*)d_in[0];
    const float* W[4] = { (const float*)d_in[1], (const float*)d_in[2],
                          (const float*)d_in[3], (const float*)d_in[4] };
    float* out = (float*)d_out;

    __nv_bfloat16 *xh, *xl, *wh, *wl, *qh, *ql, *kh, *kl, *vh, *vl, *atth, *attl;
    cudaGetSymbolAddress((void**)&xh, g_xh);
    cudaGetSymbolAddress((void**)&xl, g_xl);
    cudaGetSymbolAddress((void**)&wh, g_wh);
    cudaGetSymbolAddress((void**)&wl, g_wl);
    cudaGetSymbolAddress((void**)&qh, g_qh);
    cudaGetSymbolAddress((void**)&ql, g_ql);
    cudaGetSymbolAddress((void**)&kh, g_kh);
    cudaGetSymbolAddress((void**)&kl, g_kl);
    cudaGetSymbolAddress((void**)&vh, g_vh);
    cudaGetSymbolAddress((void**)&vl, g_vl);
    cudaGetSymbolAddress((void**)&atth, g_atth);
    cudaGetSymbolAddress((void**)&attl, g_attl);

    const int smem_gemm = 2 * STAGESZ;          // 81920 B
    cudaFuncSetAttribute(gemm_qkv_kernel, cudaFuncAttributeMaxDynamicSharedMemorySize, smem_gemm);
    cudaFuncSetAttribute(gemm_out_kernel, cudaFuncAttributeMaxDynamicSharedMemorySize, smem_gemm);
    cudaFuncSetAttribute(flash_tc_kernel, cudaFuncAttributeMaxDynamicSharedMemorySize, FSMEM);

    // 1. split-convert inputs
    int n4x = MTOT * DMODEL / 4;
    cvt_split_kernel<<<(n4x + 255) / 256, 256>>>((const float4*)x, (uint2*)xh, (uint2*)xl, n4x);
    int n4w = DD / 4;
    for (int i = 0; i < 4; ++i)
        cvt_split_kernel<<<(n4w + 255) / 256, 256>>>((const float4*)W[i],
            (uint2*)(wh + (size_t)i * DD), (uint2*)(wl + (size_t)i * DD), n4w);

    // 2. fused Q/K/V projections
    dim3 qkvgrid(DMODEL / 128, MTOT / 128, 3);
    gemm_qkv_kernel<<<qkvgrid, 256, smem_gemm>>>(xh, xl, wh, wl, qh, ql, kh, kl, vh, vl);

    // 3. tensor-core flash attention
    dim3 fgrid(SEQ / 128, BATCH * NHEADS);      // (16, 32)
    flash_tc_kernel<<<fgrid, 256, FSMEM>>>(qh, ql, kh, kl, vh, vl, atth, attl);

    // 4. output projection
    dim3 ogrid(DMODEL / 128, MTOT / 128);
    gemm_out_kernel<<<ogrid, 256, smem_gemm>>>(atth, attl, wh + 3 * (size_t)DD, wl + 3 * (size_t)DD, out);
}

// round 7
// speedup vs baseline: 4.8185x; 1.0197x over previous
#include <cuda_runtime.h>
#include <cuda_bf16.h>
#include <cstdint>
#include <math.h>

#define BATCH   2
#define SEQ     2048
#define DMODEL  1024
#define NHEADS  16
#define DK      64
#define MTOT    (BATCH * SEQ)          // 4096
#define DD      (DMODEL * DMODEL)

// ---------------------------------------------------------------------------
// Scratch (device globals; no allocation allowed)
// ---------------------------------------------------------------------------
__device__ __align__(16) __nv_bfloat16 g_xh[MTOT * DMODEL];
__device__ __align__(16) __nv_bfloat16 g_xl[MTOT * DMODEL];
__device__ __align__(16) __nv_bfloat16 g_wh[4][DD];
__device__ __align__(16) __nv_bfloat16 g_wl[4][DD];
__device__ __align__(16) __nv_bfloat16 g_qh[BATCH * NHEADS * SEQ * DK];  // [B,H,S,DK]
__device__ __align__(16) __nv_bfloat16 g_ql[BATCH * NHEADS * SEQ * DK];
__device__ __align__(16) __nv_bfloat16 g_kh[BATCH * NHEADS * SEQ * DK];
__device__ __align__(16) __nv_bfloat16 g_kl[BATCH * NHEADS * SEQ * DK];
__device__ __align__(16) __nv_bfloat16 g_vh[BATCH * NHEADS * SEQ * DK];
__device__ __align__(16) __nv_bfloat16 g_vl[BATCH * NHEADS * SEQ * DK];
__device__ __align__(16) __nv_bfloat16 g_atth[MTOT * DMODEL];            // [B,S,H*DK]
__device__ __align__(16) __nv_bfloat16 g_attl[MTOT * DMODEL];

// ---------------------------------------------------------------------------
// PTX helpers (baseline sm_80/90 features only)
// ---------------------------------------------------------------------------
__device__ __forceinline__ uint32_t smem_u32(const void* p) {
    uint32_t a;
    asm("{ .reg .u64 t; cvta.to.shared.u64 t, %1; cvt.u32.u64 %0, t; }" : "=r"(a) : "l"(p));
    return a;
}
#define CP_ASYNC16(dst, src) \
    asm volatile("cp.async.cg.shared.global [%0], [%1], 16;" :: "r"(dst), "l"(src) : "memory")
#define CP_COMMIT() asm volatile("cp.async.commit_group;" ::: "memory")
#define CP_WAIT1()  asm volatile("cp.async.wait_group 1;" ::: "memory")
#define CP_WAIT0()  asm volatile("cp.async.wait_group 0;" ::: "memory")
#define LDSM4(r0, r1, r2, r3, addr) \
    asm volatile("ldmatrix.sync.aligned.m8n8.x4.shared.b16 {%0,%1,%2,%3}, [%4];" \
        : "=r"(r0), "=r"(r1), "=r"(r2), "=r"(r3) : "r"(addr))
#define LDSM4T(r0, r1, r2, r3, addr) \
    asm volatile("ldmatrix.sync.aligned.m8n8.x4.trans.shared.b16 {%0,%1,%2,%3}, [%4];" \
        : "=r"(r0), "=r"(r1), "=r"(r2), "=r"(r3) : "r"(addr))
#define MMA16816(d, a, b0, b1) \
    asm volatile("mma.sync.aligned.m16n8k16.row.col.f32.bf16.bf16.f32 " \
        "{%0,%1,%2,%3}, {%4,%5,%6,%7}, {%8,%9}, {%0,%1,%2,%3};" \
        : "+f"((d)[0]), "+f"((d)[1]), "+f"((d)[2]), "+f"((d)[3]) \
        : "r"((a)[0]), "r"((a)[1]), "r"((a)[2]), "r"((a)[3]), "r"(b0), "r"(b1))

__device__ __forceinline__ uint32_t pack_bf16_hi(float x, float y) {
    __nv_bfloat162 h = __float22bfloat162_rn(make_float2(x, y));
    return *(uint32_t*)&h;
}
__device__ __forceinline__ uint32_t pack_bf16_lo(float x, float y, uint32_t hi) {
    __nv_bfloat162 h = *(__nv_bfloat162*)&hi;
    __nv_bfloat162 l = __float22bfloat162_rn(make_float2(
        x - __bfloat162float(h.x), y - __bfloat162float(h.y)));
    return *(uint32_t*)&l;
}

// ---------------------------------------------------------------------------
// Fused fp32 -> (hi, lo) bf16 split conversion for x + all 4 weights
// ---------------------------------------------------------------------------
#define N4X (MTOT * DMODEL / 4)     // 1048576
#define N4W (DD / 4)                // 262144 = 2^18

__global__ __launch_bounds__(256)
void cvt_all_kernel(const float4* __restrict__ x,
                    const float4* __restrict__ w0, const float4* __restrict__ w1,
                    const float4* __restrict__ w2, const float4* __restrict__ w3,
                    uint2* __restrict__ xh, uint2* __restrict__ xl,
                    uint2* __restrict__ wh, uint2* __restrict__ wl)
{
    int i = blockIdx.x * blockDim.x + threadIdx.x;
    float4 v;
    uint2 *dh, *dl;
    if (i < N4X) {
        v = x[i]; dh = xh + i; dl = xl + i;
    } else {
        int j = i - N4X;
        int w = j >> 18;
        int k = j & (N4W - 1);
        const float4* src = (w == 0) ? w0 : (w == 1) ? w1 : (w == 2) ? w2 : w3;
        v = src[k];
        dh = wh + ((size_t)w << 18) + k;
        dl = wl + ((size_t)w << 18) + k;
    }
    uint32_t h01 = pack_bf16_hi(v.x, v.y);
    uint32_t h23 = pack_bf16_hi(v.z, v.w);
    uint32_t l01 = pack_bf16_lo(v.x, v.y, h01);
    uint32_t l23 = pack_bf16_lo(v.z, v.w, h23);
    *dh = make_uint2(h01, h23);
    *dl = make_uint2(l01, l23);
}

// ---------------------------------------------------------------------------
// Split-bf16 3-term GEMM core. 128x128 tile/CTA, BK=32, 8 warps of 64x32.
// 3-stage cp.async pipeline (wait -> sync -> issue: race-free), term-outer MMAs.
// ---------------------------------------------------------------------------
#define PITCH   80                   // smem row pitch bytes (40 bf16)
#define MATSZ   (128 * PITCH)        // 10240 B per matrix tile
#define STAGESZ (4 * MATSZ)          // Ah, Al, Bh, Bl
#define NSTG    3
#define NKCH    (DMODEL / 32)        // 32 chunks

template <typename Epi>
__device__ __forceinline__
void gemm_core(const __nv_bfloat16* Ah, const __nv_bfloat16* Al,
               const __nv_bfloat16* Bh, const __nv_bfloat16* Bl,
               int bm, int bn, Epi epi)
{
    extern __shared__ char smem[];
    const uint32_t sbase = smem_u32(smem);
    const int t    = threadIdx.x;
    const int wid  = t >> 5;
    const int lane = t & 31;
    const int wm   = (wid >> 2) * 64;
    const int wn   = (wid & 3) * 32;

    auto load_stage = [&](int c, int st) {
        const int k0 = c * 32;
        const uint32_t sb = sbase + st * STAGESZ;
#pragma unroll
        for (int i = 0; i < 8; ++i) {
            int idx = t + i * 256;
            int mat = idx >> 9;
            int r   = (idx >> 2) & 127;
            int cc  = idx & 3;
            const __nv_bfloat16* src;
            if      (mat == 0) src = Ah + (size_t)(bm + r) * DMODEL + k0 + cc * 8;
            else if (mat == 1) src = Al + (size_t)(bm + r) * DMODEL + k0 + cc * 8;
            else if (mat == 2) src = Bh + (size_t)(bn + r) * DMODEL + k0 + cc * 8;
            else               src = Bl + (size_t)(bn + r) * DMODEL + k0 + cc * 8;
            CP_ASYNC16(sb + mat * MATSZ + r * PITCH + cc * 16, src);
        }
        CP_COMMIT();
    };

    float acc[4][4][4];
#pragma unroll
    for (int i = 0; i < 4; ++i)
#pragma unroll
        for (int j = 0; j < 4; ++j)
#pragma unroll
            for (int k = 0; k < 4; ++k) acc[i][j][k] = 0.f;

    const int a_row = lane & 15;
    const int a_kb  = (lane >> 4) * 16;
    const int b_row = ((lane >> 4) & 1) * 8 + (lane & 7);
    const int b_kb  = ((lane >> 3) & 1) * 16;

    load_stage(0, 0);
    load_stage(1, 1);

    for (int c = 0; c < NKCH; ++c) {
        if (c + 1 < NKCH) CP_WAIT1(); else CP_WAIT0();
        __syncthreads();
        // safe: all warps passed the barrier => finished reading stage (c-1),
        // whose buffer (c+2)%3 we now overwrite
        if (c + 2 < NKCH) load_stage(c + 2, (c + 2) % NSTG);

        const uint32_t sA = sbase + (c % NSTG) * STAGESZ;
        const uint32_t sB = sA + 2 * MATSZ;

#pragma unroll
        for (int kk = 0; kk < 64; kk += 32) {
            uint32_t ah[4][4], al[4][4], bh[4][2], bl[4][2];
#pragma unroll
            for (int mt = 0; mt < 4; ++mt) {
                uint32_t ra = sA + (wm + mt * 16 + a_row) * PITCH + kk + a_kb;
                LDSM4(ah[mt][0], ah[mt][1], ah[mt][2], ah[mt][3], ra);
                LDSM4(al[mt][0], al[mt][1], al[mt][2], al[mt][3], ra + MATSZ);
            }
#pragma unroll
            for (int np = 0; np < 2; ++np) {
                uint32_t rb = sB + (wn + np * 16 + b_row) * PITCH + kk + b_kb;
                uint32_t r0, r1, r2, r3;
                LDSM4(r0, r1, r2, r3, rb);
                bh[np * 2][0] = r0; bh[np * 2][1] = r1;
                bh[np * 2 + 1][0] = r2; bh[np * 2 + 1][1] = r3;
                LDSM4(r0, r1, r2, r3, rb + MATSZ);
                bl[np * 2][0] = r0; bl[np * 2][1] = r1;
                bl[np * 2 + 1][0] = r2; bl[np * 2 + 1][1] = r3;
            }
            // term-outer: 16 independent MMAs per term => dependency distance 16
#pragma unroll
            for (int mt = 0; mt < 4; ++mt)
#pragma unroll
                for (int nt = 0; nt < 4; ++nt)
                    MMA16816(acc[mt][nt], ah[mt], bh[nt][0], bh[nt][1]);
#pragma unroll
            for (int mt = 0; mt < 4; ++mt)
#pragma unroll
                for (int nt = 0; nt < 4; ++nt)
                    MMA16816(acc[mt][nt], ah[mt], bl[nt][0], bl[nt][1]);
#pragma unroll
            for (int mt = 0; mt < 4; ++mt)
#pragma unroll
                for (int nt = 0; nt < 4; ++nt)
                    MMA16816(acc[mt][nt], al[mt], bh[nt][0], bh[nt][1]);
        }
    }

    // epilogue callback per float2 fragment
#pragma unroll
    for (int mt = 0; mt < 4; ++mt)
#pragma unroll
        for (int nt = 0; nt < 4; ++nt) {
            int m0 = bm + wm + mt * 16 + (lane >> 2);
            int n0 = bn + wn + nt * 8 + 2 * (lane & 3);
#pragma unroll
            for (int hhalf = 0; hhalf < 2; ++hhalf)
                epi(m0 + hhalf * 8, n0, acc[mt][nt][hhalf * 2], acc[mt][nt][hhalf * 2 + 1]);
        }
}

// Fused Q/K/V projection
__global__ __launch_bounds__(256, 1)
void gemm_qkv_kernel(const __nv_bfloat16* __restrict__ xh,
                     const __nv_bfloat16* __restrict__ xl,
                     const __nv_bfloat16* __restrict__ wh,
                     const __nv_bfloat16* __restrict__ wl,
                     __nv_bfloat16* __restrict__ qh, __nv_bfloat16* __restrict__ ql,
                     __nv_bfloat16* __restrict__ kh, __nv_bfloat16* __restrict__ kl,
                     __nv_bfloat16* __restrict__ vh, __nv_bfloat16* __restrict__ vl)
{
    const int z = blockIdx.z;
    const __nv_bfloat16* Bh = wh + (size_t)z * DD;
    const __nv_bfloat16* Bl = wl + (size_t)z * DD;
    __nv_bfloat16* Yh = (z == 0) ? qh : (z == 1) ? kh : vh;
    __nv_bfloat16* Yl = (z == 0) ? ql : (z == 1) ? kl : vl;
    const float scale = (z == 0) ? 0.125f : 1.0f;

    gemm_core(xh, xl, Bh, Bl, blockIdx.y * 128, blockIdx.x * 128,
        [&](int m, int n, float v0, float v1) {
            v0 *= scale; v1 *= scale;
            uint32_t hp = pack_bf16_hi(v0, v1);
            uint32_t lp = pack_bf16_lo(v0, v1, hp);
            int bb = m >> 11, s = m & 2047, hh = n >> 6, dd = n & 63;
            size_t off = (((size_t)(bb * NHEADS + hh) * SEQ) + s) * DK + dd;
            *(uint32_t*)&Yh[off] = hp;
            *(uint32_t*)&Yl[off] = lp;
        });
}

// Output projection: fp32 result
__global__ __launch_bounds__(256, 1)
void gemm_out_kernel(const __nv_bfloat16* __restrict__ ah,
                     const __nv_bfloat16* __restrict__ al,
                     const __nv_bfloat16* __restrict__ bh,
                     const __nv_bfloat16* __restrict__ bl,
                     float* __restrict__ Y)
{
    gemm_core(ah, al, bh, bl, blockIdx.y * 128, blockIdx.x * 128,
        [&](int m, int n, float v0, float v1) {
            *(float2*)&Y[(size_t)m * DMODEL + n] = make_float2(v0, v1);
        });
}

// ---------------------------------------------------------------------------
// Tensor-core flash attention (causal). Term-outer MMA ordering.
// ---------------------------------------------------------------------------
#define ROWB   144                    // smem row pitch bytes (72 bf16)
#define FQ_SZ  (128 * ROWB)           // 18432 per Q matrix
#define FKV_SZ (64 * ROWB)            // 9216 per K/V matrix
#define FSTAGE (4 * FKV_SZ)           // KH, KL, VH, VL
#define FSMEM  (2 * FQ_SZ + 2 * FSTAGE)  // 110592

__device__ __forceinline__ float fexp2(float t) {
    t = fmaxf(t, -126.f);
    float r = rintf(t);
    float f = t - r;
    float p =            0.0013333558f;
    p = fmaf(p, f, 0.0096181291f);
    p = fmaf(p, f, 0.0555041087f);
    p = fmaf(p, f, 0.2402265069f);
    p = fmaf(p, f, 0.6931471806f);
    p = fmaf(p, f, 1.0f);
    return p * __int_as_float(((int)r + 127) << 23);
}

__global__ __launch_bounds__(256, 1)
void flash_tc_kernel(const __nv_bfloat16* __restrict__ Qh,
                     const __nv_bfloat16* __restrict__ Ql,
                     const __nv_bfloat16* __restrict__ Kh,
                     const __nv_bfloat16* __restrict__ Kl,
                     const __nv_bfloat16* __restrict__ Vh,
                     const __nv_bfloat16* __restrict__ Vl,
                     __nv_bfloat16* __restrict__ Oh,
                     __nv_bfloat16* __restrict__ Ol)
{
    extern __shared__ char smem[];
    const uint32_t sbase = smem_u32(smem);
    const int t    = threadIdx.x;
    const int wid  = t >> 5;
    const int lane = t & 31;
    const int bh   = blockIdx.y;
    const int b    = bh >> 4;
    const int h    = bh & 15;
    const int qt   = gridDim.x - 1 - blockIdx.x;   // long CTAs first
    const int q0   = qt * 128;
    const int wm   = wid * 16;
    const int ntiles = 2 * qt + 2;

    const size_t headoff = (size_t)(b * NHEADS + h) * SEQ * DK;

    // --- preamble: load Q (hi+lo) then stage 0 of K/V ---
    {
#pragma unroll
        for (int i = 0; i < 8; ++i) {
            int idx = t + i * 256;
            int arr = idx >> 10;
            int c   = idx & 1023;
            int r   = c >> 3;
            int ch  = c & 7;
            const __nv_bfloat16* src = (arr ? Ql : Qh) + headoff + (size_t)(q0 + r) * DK + ch * 8;
            CP_ASYNC16(sbase + arr * FQ_SZ + r * ROWB + ch * 16, src);
        }
        CP_COMMIT();
    }
    auto load_kv = [&](int kt, int st) {
        const int k0 = kt * 64;
        const uint32_t sb = sbase + 2 * FQ_SZ + st * FSTAGE;
#pragma unroll
        for (int i = 0; i < 8; ++i) {
            int idx = t + i * 256;
            int arr = idx >> 9;
            int c   = idx & 511;
            int r   = c >> 3;
            int ch  = c & 7;
            const __nv_bfloat16* base = (arr == 0) ? Kh : (arr == 1) ? Kl : (arr == 2) ? Vh : Vl;
            const __nv_bfloat16* src = base + headoff + (size_t)(k0 + r) * DK + ch * 8;
            CP_ASYNC16(sb + arr * FKV_SZ + r * ROWB + ch * 16, src);
        }
        CP_COMMIT();
    };
    load_kv(0, 0);

    CP_WAIT1();
    __syncthreads();

    // --- preload Q fragments ---
    uint32_t qfh[4][4], qfl[4][4];
    {
        const int a_row = lane & 15;
        const int a_kb  = (lane >> 4) * 16;
#pragma unroll
        for (int kk = 0; kk < 4; ++kk) {
            uint32_t ra = sbase + (wm + a_row) * ROWB + kk * 32 + a_kb;
            LDSM4(qfh[kk][0], qfh[kk][1], qfh[kk][2], qfh[kk][3], ra);
            LDSM4(qfl[kk][0], qfl[kk][1], qfl[kk][2], qfl[kk][3], ra + FQ_SZ);
        }
    }

    const int b_row = ((lane >> 4) & 1) * 8 + (lane & 7);
    const int b_kb  = ((lane >> 3) & 1) * 16;
    const int vrow  = lane & 15;
    const int vcb   = (lane >> 4) * 8;
    const float L2E = 1.4426950408889634f;

    float o[8][4];
#pragma unroll
    for (int i = 0; i < 8; ++i)
#pragma unroll
        for (int j = 0; j < 4; ++j) o[i][j] = 0.f;
    float m_s[2] = {-INFINITY, -INFINITY};
    float l_s[2] = {0.f, 0.f};

    for (int kt = 0; kt < ntiles; ++kt) {
        CP_WAIT0();
        __syncthreads();
        if (kt + 1 < ntiles) load_kv(kt + 1, (kt + 1) & 1);

        const uint32_t stg = sbase + 2 * FQ_SZ + (kt & 1) * FSTAGE;
        const int k0 = kt * 64;

        // ---- scores: S = Q K^T (3-term), term-outer ----
        float s[8][4];
#pragma unroll
        for (int i = 0; i < 8; ++i)
#pragma unroll
            for (int j = 0; j < 4; ++j) s[i][j] = 0.f;

#pragma unroll
        for (int kk = 0; kk < 4; ++kk) {
            uint32_t khf[4][4], klf[4][4];
#pragma unroll
            for (int nt2 = 0; nt2 < 4; ++nt2) {
                uint32_t addr = stg + (nt2 * 16 + b_row) * ROWB + kk * 32 + b_kb;
                LDSM4(khf[nt2][0], khf[nt2][1], khf[nt2][2], khf[nt2][3], addr);
                LDSM4(klf[nt2][0], klf[nt2][1], klf[nt2][2], klf[nt2][3], addr + FKV_SZ);
            }
#pragma unroll
            for (int nt2 = 0; nt2 < 4; ++nt2) {
                MMA16816(s[nt2 * 2],     qfh[kk], khf[nt2][0], khf[nt2][1]);
                MMA16816(s[nt2 * 2 + 1], qfh[kk], khf[nt2][2], khf[nt2][3]);
            }
#pragma unroll
            for (int nt2 = 0; nt2 < 4; ++nt2) {
                MMA16816(s[nt2 * 2],     qfh[kk], klf[nt2][0], klf[nt2][1]);
                MMA16816(s[nt2 * 2 + 1], qfh[kk], klf[nt2][2], klf[nt2][3]);
            }
#pragma unroll
            for (int nt2 = 0; nt2 < 4; ++nt2) {
                MMA16816(s[nt2 * 2],     qfl[kk], khf[nt2][0], khf[nt2][1]);
                MMA16816(s[nt2 * 2 + 1], qfl[kk], khf[nt2][2], khf[nt2][3]);
            }
        }

        // ---- causal mask ----
        if (k0 + 63 > q0 + wm) {
#pragma unroll
            for (int nt = 0; nt < 8; ++nt)
#pragma unroll
                for (int c = 0; c < 4; ++c) {
                    int col = k0 + nt * 8 + 2 * (lane & 3) + (c & 1);
                    int row = q0 + wm + (lane >> 2) + (c >> 1) * 8;
                    if (col > row) s[nt][c] = -INFINITY;
                }
        }

        // ---- online softmax ----
#pragma unroll
        for (int r = 0; r < 2; ++r) {
            float rm = -INFINITY;
#pragma unroll
            for (int nt = 0; nt < 8; ++nt)
                rm = fmaxf(rm, fmaxf(s[nt][r * 2], s[nt][r * 2 + 1]));
            rm = fmaxf(rm, __shfl_xor_sync(0xffffffffu, rm, 1));
            rm = fmaxf(rm, __shfl_xor_sync(0xffffffffu, rm, 2));
            float mnew = fmaxf(m_s[r], rm);
            float corr = fexp2((m_s[r] - mnew) * L2E);
            l_s[r] *= corr;
#pragma unroll
            for (int dn = 0; dn < 8; ++dn) {
                o[dn][r * 2]     *= corr;
                o[dn][r * 2 + 1] *= corr;
            }
            m_s[r] = mnew;
            float ps = 0.f;
#pragma unroll
            for (int nt = 0; nt < 8; ++nt) {
                float p0 = fexp2((s[nt][r * 2]     - mnew) * L2E);
                float p1 = fexp2((s[nt][r * 2 + 1] - mnew) * L2E);
                s[nt][r * 2] = p0; s[nt][r * 2 + 1] = p1;
                ps += p0 + p1;
            }
            ps += __shfl_xor_sync(0xffffffffu, ps, 1);
            ps += __shfl_xor_sync(0xffffffffu, ps, 2);
            l_s[r] += ps;
        }

        // ---- O += P @ V (3-term), term-outer ----
#pragma unroll
        for (int kk = 0; kk < 4; ++kk) {
            const int t0 = 2 * kk, t1 = 2 * kk + 1;
            uint32_t pah[4], pal[4];
            pah[0] = pack_bf16_hi(s[t0][0], s[t0][1]);
            pah[1] = pack_bf16_hi(s[t0][2], s[t0][3]);
            pah[2] = pack_bf16_hi(s[t1][0], s[t1][1]);
            pah[3] = pack_bf16_hi(s[t1][2], s[t1][3]);
            pal[0] = pack_bf16_lo(s[t0][0], s[t0][1], pah[0]);
            pal[1] = pack_bf16_lo(s[t0][2], s[t0][3], pah[1]);
            pal[2] = pack_bf16_lo(s[t1][0], s[t1][1], pah[2]);
            pal[3] = pack_bf16_lo(s[t1][2], s[t1][3], pah[3]);
            uint32_t vhf[4][4], vlf[4][4];
#pragma unroll
            for (int dp = 0; dp < 4; ++dp) {
                uint32_t vaddr = stg + 2 * FKV_SZ + (kk * 16 + vrow) * ROWB + (dp * 16 + vcb) * 2;
                LDSM4T(vhf[dp][0], vhf[dp][1], vhf[dp][2], vhf[dp][3], vaddr);
                LDSM4T(vlf[dp][0], vlf[dp][1], vlf[dp][2], vlf[dp][3], vaddr + FKV_SZ);
            }
#pragma unroll
            for (int dp = 0; dp < 4; ++dp) {
                MMA16816(o[dp * 2],     pah, vhf[dp][0], vhf[dp][1]);
                MMA16816(o[dp * 2 + 1], pah, vhf[dp][2], vhf[dp][3]);
            }
#pragma unroll
            for (int dp = 0; dp < 4; ++dp) {
                MMA16816(o[dp * 2],     pal, vhf[dp][0], vhf[dp][1]);
                MMA16816(o[dp * 2 + 1], pal, vhf[dp][2], vhf[dp][3]);
            }
#pragma unroll
            for (int dp = 0; dp < 4; ++dp) {
                MMA16816(o[dp * 2],     pah, vlf[dp][0], vlf[dp][1]);
                MMA16816(o[dp * 2 + 1], pah, vlf[dp][2], vlf[dp][3]);
            }
        }
    }

    // ---- normalize + split-store to ATT [B,S,H*DK] ----
    const float inv0 = 1.f / l_s[0];
    const float inv1 = 1.f / l_s[1];
    const int row0 = q0 + wm + (lane >> 2);
    const int colb = h * DK + 2 * (lane & 3);
#pragma unroll
    for (int dn = 0; dn < 8; ++dn) {
        int col = colb + dn * 8;
        {
            float v0 = o[dn][0] * inv0, v1 = o[dn][1] * inv0;
            uint32_t hp = pack_bf16_hi(v0, v1);
            uint32_t lp = pack_bf16_lo(v0, v1, hp);
            size_t off = (size_t)(b * SEQ + row0) * DMODEL + col;
            *(uint32_t*)&Oh[off] = hp;
            *(uint32_t*)&Ol[off] = lp;
        }
        {
            float v0 = o[dn][2] * inv1, v1 = o[dn][3] * inv1;
            uint32_t hp = pack_bf16_hi(v0, v1);
            uint32_t lp = pack_bf16_lo(v0, v1, hp);
            size_t off = (size_t)(b * SEQ + row0 + 8) * DMODEL + col;
            *(uint32_t*)&Oh[off] = hp;
            *(uint32_t*)&Ol[off] = lp;
        }
    }
}

// ---------------------------------------------------------------------------
// Launch
// ---------------------------------------------------------------------------
extern "C" void kernel_launch(void* const* d_in, const int* in_sizes, int n_in,
                              void* d_out, int out_size)
{
    const float* x = (const float*)d_in[0];
    const float* W[4] = { (const float*)d_in[1], (const float*)d_in[2],
                          (const float*)d_in[3], (const float*)d_in[4] };
    float* out = (float*)d_out;

    __nv_bfloat16 *xh, *xl, *wh, *wl, *qh, *ql, *kh, *kl, *vh, *vl, *atth, *attl;
    cudaGetSymbolAddress((void**)&xh, g_xh);
    cudaGetSymbolAddress((void**)&xl, g_xl);
    cudaGetSymbolAddress((void**)&wh, g_wh);
    cudaGetSymbolAddress((void**)&wl, g_wl);
    cudaGetSymbolAddress((void**)&qh, g_qh);
    cudaGetSymbolAddress((void**)&ql, g_ql);
    cudaGetSymbolAddress((void**)&kh, g_kh);
    cudaGetSymbolAddress((void**)&kl, g_kl);
    cudaGetSymbolAddress((void**)&vh, g_vh);
    cudaGetSymbolAddress((void**)&vl, g_vl);
    cudaGetSymbolAddress((void**)&atth, g_atth);
    cudaGetSymbolAddress((void**)&attl, g_attl);

    const int smem_gemm = NSTG * STAGESZ;       // 122880 B
    cudaFuncSetAttribute(gemm_qkv_kernel, cudaFuncAttributeMaxDynamicSharedMemorySize, smem_gemm);
    cudaFuncSetAttribute(gemm_out_kernel, cudaFuncAttributeMaxDynamicSharedMemorySize, smem_gemm);
    cudaFuncSetAttribute(flash_tc_kernel, cudaFuncAttributeMaxDynamicSharedMemorySize, FSMEM);

    // 1. fused split-convert of x + 4 weights (one launch)
    int n4tot = N4X + 4 * N4W;                  // 2097152
    cvt_all_kernel<<<n4tot / 256, 256>>>((const float4*)x,
        (const float4*)W[0], (const float4*)W[1], (const float4*)W[2], (const float4*)W[3],
        (uint2*)xh, (uint2*)xl, (uint2*)wh, (uint2*)wl);

    // 2. fused Q/K/V projections
    dim3 qkvgrid(DMODEL / 128, MTOT / 128, 3);
    gemm_qkv_kernel<<<qkvgrid, 256, smem_gemm>>>(xh, xl, wh, wl, qh, ql, kh, kl, vh, vl);

    // 3. tensor-core flash attention
    dim3 fgrid(SEQ / 128, BATCH * NHEADS);      // (16, 32)
    flash_tc_kernel<<<fgrid, 256, FSMEM>>>(qh, ql, kh, kl, vh, vl, atth, attl);

    // 4. output projection
    dim3 ogrid(DMODEL / 128, MTOT / 128);
    gemm_out_kernel<<<ogrid, 256, smem_gemm>>>(atth, attl, wh + 3 * (size_t)DD, wl + 3 * (size_t)DD, out);
}